// round 3
// baseline (speedup 1.0000x reference)
#include <cuda_runtime.h>
#include <cstdint>

#define H      128
#define INW    86
#define OUTW   66
#define GATES  512
#define TSEQ   50
#define NSTEP  65   // 50 scan + 1 replay of x[:,49] + 14 rollout
#define RSTEPS 15
#define BT     32   // batch rows per block
#define PITCH  36   // padded row pitch: multiple of 4 for 16B-aligned pair loads
#define NTHR   512

typedef unsigned long long ull;

// ---- weight scratch: gate-interleaved float4 [kk][k] = {w_i, w_f, w_g, w_o} ----
__device__ float4 g_W0i[INW * H];   // from Wih0 [512][86]
__device__ float4 g_W0h[H   * H];   // from Whh0 [512][128]
__device__ float4 g_W1i[H   * H];   // from Wih1 [512][128]
__device__ float4 g_W1h[H   * H];   // from Whh1 [512][128]
__device__ float  g_WdT[H * OUTW];  // Wd^T : [kk][o]
__device__ float  g_b0[GATES];
__device__ float  g_b1[GATES];

// ---- packed f32x2 helpers (Blackwell FFMA2 via PTX) ----
__device__ __forceinline__ ull splat2(float v){ ull r; asm("mov.b64 %0, {%1, %1};" : "=l"(r) : "f"(v)); return r; }
__device__ __forceinline__ ull pack2(float x, float y){ ull r; asm("mov.b64 %0, {%1, %2};" : "=l"(r) : "f"(x), "f"(y)); return r; }
__device__ __forceinline__ float2 unpack2(ull a){ float2 f; asm("mov.b64 {%0, %1}, %2;" : "=f"(f.x), "=f"(f.y) : "l"(a)); return f; }
__device__ __forceinline__ ull fma2(ull a, ull b, ull c){ ull d; asm("fma.rn.f32x2 %0, %1, %2, %3;" : "=l"(d) : "l"(a), "l"(b), "l"(c)); return d; }

// fast activations: sigma via EX2+RCP, tanh(x) = 2*sigma(2x) - 1
__device__ __forceinline__ float sigf(float x){ return __fdividef(1.0f, 1.0f + __expf(-x)); }
__device__ __forceinline__ float tanhfast(float x){ return __fdividef(2.0f, 1.0f + __expf(-2.0f * x)) - 1.0f; }

// Accumulate gates over K for 4 row-pairs (8 rows). Pointer-increment form.
template<int K>
__device__ __forceinline__ void accum(ull acc[4][4], const float4* __restrict__ W4,
                                      const float* src, int k, int rbase)
{
  const float4* wp = W4 + k;
  const float*  sp = src + rbase;
  #pragma unroll 4
  for (int kk = 0; kk < K; ++kk) {
    float4 w = __ldg(wp);  wp += H;
    ull s0 = splat2(w.x), s1 = splat2(w.y), s2 = splat2(w.z), s3 = splat2(w.w);
    ulonglong2 ua = *reinterpret_cast<const ulonglong2*>(sp);
    ulonglong2 ub = *reinterpret_cast<const ulonglong2*>(sp + 4);
    sp += PITCH;
    acc[0][0] = fma2(ua.x, s0, acc[0][0]);
    acc[1][0] = fma2(ua.x, s1, acc[1][0]);
    acc[2][0] = fma2(ua.x, s2, acc[2][0]);
    acc[3][0] = fma2(ua.x, s3, acc[3][0]);
    acc[0][1] = fma2(ua.y, s0, acc[0][1]);
    acc[1][1] = fma2(ua.y, s1, acc[1][1]);
    acc[2][1] = fma2(ua.y, s2, acc[2][1]);
    acc[3][1] = fma2(ua.y, s3, acc[3][1]);
    acc[0][2] = fma2(ub.x, s0, acc[0][2]);
    acc[1][2] = fma2(ub.x, s1, acc[1][2]);
    acc[2][2] = fma2(ub.x, s2, acc[2][2]);
    acc[3][2] = fma2(ub.x, s3, acc[3][2]);
    acc[0][3] = fma2(ub.y, s0, acc[0][3]);
    acc[1][3] = fma2(ub.y, s1, acc[1][3]);
    acc[2][3] = fma2(ub.y, s2, acc[2][3]);
    acc[3][3] = fma2(ub.y, s3, acc[3][3]);
  }
}

// i,f,g,o -> (c,h) update for 4 row-pairs
__device__ __forceinline__ void cell_update(ull acc[4][4], ull cst[4], ull hn[4])
{
  #pragma unroll
  for (int p = 0; p < 4; ++p) {
    float2 gi = unpack2(acc[0][p]);
    float2 gf = unpack2(acc[1][p]);
    float2 gg = unpack2(acc[2][p]);
    float2 go = unpack2(acc[3][p]);
    float2 c  = unpack2(cst[p]);
    float cx = sigf(gf.x) * c.x + sigf(gi.x) * tanhfast(gg.x);
    float cy = sigf(gf.y) * c.y + sigf(gi.y) * tanhfast(gg.y);
    float hx = sigf(go.x) * tanhfast(cx);
    float hy = sigf(go.y) * tanhfast(cy);
    cst[p] = pack2(cx, cy);
    hn[p]  = pack2(hx, hy);
  }
}

// ---- weight rearrange / bias fuse (tiny, once per launch) ----
__global__ void prep_kernel(const float* __restrict__ Wih0, const float* __restrict__ Whh0,
                            const float* __restrict__ bih0, const float* __restrict__ bhh0,
                            const float* __restrict__ Wih1, const float* __restrict__ Whh1,
                            const float* __restrict__ bih1, const float* __restrict__ bhh1,
                            const float* __restrict__ Wd)
{
  int j = blockIdx.x * blockDim.x + threadIdx.x;
  if (j < GATES * INW) {
    int r = j / INW, kk = j % INW;
    reinterpret_cast<float*>(g_W0i)[(kk * H + (r & 127)) * 4 + (r >> 7)] = Wih0[j];
    return;
  }
  j -= GATES * INW;
  if (j < GATES * H) {
    int r = j / H, kk = j % H;
    reinterpret_cast<float*>(g_W0h)[(kk * H + (r & 127)) * 4 + (r >> 7)] = Whh0[j];
    return;
  }
  j -= GATES * H;
  if (j < GATES * H) {
    int r = j / H, kk = j % H;
    reinterpret_cast<float*>(g_W1i)[(kk * H + (r & 127)) * 4 + (r >> 7)] = Wih1[j];
    return;
  }
  j -= GATES * H;
  if (j < GATES * H) {
    int r = j / H, kk = j % H;
    reinterpret_cast<float*>(g_W1h)[(kk * H + (r & 127)) * 4 + (r >> 7)] = Whh1[j];
    return;
  }
  j -= GATES * H;
  if (j < OUTW * H) { g_WdT[(j % H) * OUTW + (j / H)] = Wd[j]; return; }
  j -= OUTW * H;
  if (j < GATES) { g_b0[j] = bih0[j] + bhh0[j]; return; }
  j -= GATES;
  if (j < GATES) { g_b1[j] = bih1[j] + bhh1[j]; return; }
}

// ---- main persistent-tile LSTM kernel ----
// Block: 32 batch rows for all 65 steps, 512 threads, 1 block/SM (16 warps).
// Thread (k = tid&127 gate unit, rg = tid>>7 in 0..3 -> 8 rows = 4 packed row-pairs).
// 4 rg-warp-groups share the same weight lines -> L1 temporal reuse; 256 blocks halve
// unique L2 weight traffic vs BT=16. h1/h2 double-buffered: 2 barriers/step.
__global__ void __launch_bounds__(NTHR, 1)
lstm_main(const float* __restrict__ x, const float* __restrict__ bd, float* __restrict__ out)
{
  __shared__ __align__(16) float uT [INW][PITCH];      // transposed step input
  __shared__ __align__(16) float h1T[2][H][PITCH];     // ping-pong
  __shared__ __align__(16) float h2T[2][H][PITCH];

  const int tid   = threadIdx.x;
  const int k     = tid & 127;
  const int rg    = tid >> 7;
  const int rbase = rg * 8;
  const int row0  = blockIdx.x * BT;

  for (int i = tid; i < 2 * H * PITCH; i += NTHR) { (&h1T[0][0][0])[i] = 0.0f; (&h2T[0][0][0])[i] = 0.0f; }

  ull c1[4], c2[4];
  #pragma unroll
  for (int p = 0; p < 4; ++p) { c1[p] = 0ull; c2[p] = 0ull; }

  ull b0p[4], b1p[4];
  #pragma unroll
  for (int g = 0; g < 4; ++g) { b0p[g] = splat2(g_b0[g * H + k]); b1p[g] = splat2(g_b1[g * H + k]); }
  const float bdv = (k < OUTW) ? bd[k] : 0.0f;

  // prestage u for step 0
  for (int i = tid; i < BT * INW; i += NTHR) {
    int r = i / INW, c = i % INW;
    uT[c][r] = x[(size_t)(row0 + r) * (TSEQ * INW) + c];
  }
  __syncthreads();

  for (int s = 0; s < NSTEP; ++s) {
    const int rd = s & 1, wr = rd ^ 1;
    ull acc[4][4], hn[4];

    // ---- layer 0 : gates = u@Wih0^T + h1@Whh0^T + b0 ----
    #pragma unroll
    for (int g = 0; g < 4; ++g)
      #pragma unroll
      for (int p = 0; p < 4; ++p) acc[g][p] = b0p[g];
    accum<INW>(acc, g_W0i, &uT[0][0],      k, rbase);
    accum<H>  (acc, g_W0h, &h1T[rd][0][0], k, rbase);
    cell_update(acc, c1, hn);
    *reinterpret_cast<ulonglong2*>(&h1T[wr][k][rbase])     = make_ulonglong2(hn[0], hn[1]);
    *reinterpret_cast<ulonglong2*>(&h1T[wr][k][rbase + 4]) = make_ulonglong2(hn[2], hn[3]);
    __syncthreads();   // barrier A: h1[wr] visible; all reads of uT done

    // stage u for next step (x path); rollout pose handled after dense head
    if (s + 1 <= TSEQ) {
      int t = (s + 1 < TSEQ) ? (s + 1) : (TSEQ - 1);
      for (int i = tid; i < BT * INW; i += NTHR) {
        int r = i / INW, c = i % INW;
        uT[c][r] = x[(size_t)(row0 + r) * (TSEQ * INW) + t * INW + c];
      }
    }

    // ---- layer 1 : gates = h1@Wih1^T + h2@Whh1^T + b1 ----
    #pragma unroll
    for (int g = 0; g < 4; ++g)
      #pragma unroll
      for (int p = 0; p < 4; ++p) acc[g][p] = b1p[g];
    accum<H>(acc, g_W1i, &h1T[wr][0][0], k, rbase);
    accum<H>(acc, g_W1h, &h2T[rd][0][0], k, rbase);
    cell_update(acc, c2, hn);
    *reinterpret_cast<ulonglong2*>(&h2T[wr][k][rbase])     = make_ulonglong2(hn[0], hn[1]);
    *reinterpret_cast<ulonglong2*>(&h2T[wr][k][rbase + 4]) = make_ulonglong2(hn[2], hn[3]);
    __syncthreads();   // barrier B: h2[wr] visible; u staging visible

    // ---- dense head (steps 50..64): pose = h2 @ Wd^T + bd ----
    if (s >= TSEQ) {
      const int so = s - TSEQ;
      if (k < OUTW) {
        ull pa[4];
        #pragma unroll
        for (int p = 0; p < 4; ++p) pa[p] = splat2(bdv);
        const float* wd = &g_WdT[k];
        const float* sp = &h2T[wr][0][rbase];
        #pragma unroll 4
        for (int kk = 0; kk < H; ++kk) {
          ull w2 = splat2(__ldg(wd));  wd += OUTW;
          ulonglong2 ua = *reinterpret_cast<const ulonglong2*>(sp);
          ulonglong2 ub = *reinterpret_cast<const ulonglong2*>(sp + 4);
          sp += PITCH;
          pa[0] = fma2(ua.x, w2, pa[0]);
          pa[1] = fma2(ua.y, w2, pa[1]);
          pa[2] = fma2(ub.x, w2, pa[2]);
          pa[3] = fma2(ub.y, w2, pa[3]);
        }
        #pragma unroll
        for (int p = 0; p < 4; ++p) {
          float2 f = unpack2(pa[p]);
          int rloc = rbase + 2 * p;
          size_t r = (size_t)(row0 + rloc);
          out[ r      * (RSTEPS * OUTW) + so * OUTW + k] = f.x;
          out[(r + 1) * (RSTEPS * OUTW) + so * OUTW + k] = f.y;
          uT[k][rloc]     = f.x;   // pose becomes next step's u[0..65]; u[66..85] keeps cond
          uT[k][rloc + 1] = f.y;
        }
      }
      __syncthreads();  // barrier C: pose in uT visible for next layer0
    }
  }
}

extern "C" void kernel_launch(void* const* d_in, const int* in_sizes, int n_in,
                              void* d_out, int out_size)
{
  const float* x    = (const float*)d_in[0];
  const float* Wih0 = (const float*)d_in[1];
  const float* Whh0 = (const float*)d_in[2];
  const float* bih0 = (const float*)d_in[3];
  const float* bhh0 = (const float*)d_in[4];
  const float* Wih1 = (const float*)d_in[5];
  const float* Whh1 = (const float*)d_in[6];
  const float* bih1 = (const float*)d_in[7];
  const float* bhh1 = (const float*)d_in[8];
  const float* Wd   = (const float*)d_in[9];
  const float* bd   = (const float*)d_in[10];
  float* out = (float*)d_out;

  const int B = in_sizes[0] / (TSEQ * INW);   // 8192

  const int prep_n = GATES * INW + 3 * GATES * H + OUTW * H + 2 * GATES;
  prep_kernel<<<(prep_n + 255) / 256, 256>>>(Wih0, Whh0, bih0, bhh0,
                                             Wih1, Whh1, bih1, bhh1, Wd);
  lstm_main<<<B / BT, NTHR>>>(x, bd, out);
}

// round 4
// speedup vs baseline: 1.2164x; 1.2164x over previous
#include <cuda_runtime.h>
#include <cstdint>

#define H      128
#define INW    86
#define OUTW   66
#define GATES  512
#define TSEQ   50
#define NSTEP  65   // 50 scan + 1 replay of x[:,49] + 14 rollout
#define RSTEPS 15
#define BT     16   // batch rows per block
#define PITCH  20   // padded row pitch: multiple of 4 for 16B-aligned pair loads
#define NTHR   256

typedef unsigned long long ull;

// ---- weight scratch: gate-interleaved float4 [kk][k] = {w_i, w_f, w_g, w_o} ----
__device__ float4 g_W0i[INW * H];   // from Wih0 [512][86]
__device__ float4 g_W0h[H   * H];   // from Whh0 [512][128]
__device__ float4 g_W1i[H   * H];   // from Wih1 [512][128]
__device__ float4 g_W1h[H   * H];   // from Whh1 [512][128]
__device__ float  g_WdT[H * OUTW];  // Wd^T : [kk][o]
__device__ float  g_b0[GATES];
__device__ float  g_b1[GATES];

// ---- packed f32x2 helpers (Blackwell FFMA2 via PTX) ----
__device__ __forceinline__ ull splat2(float v){ ull r; asm("mov.b64 %0, {%1, %1};" : "=l"(r) : "f"(v)); return r; }
__device__ __forceinline__ ull pack2(float x, float y){ ull r; asm("mov.b64 %0, {%1, %2};" : "=l"(r) : "f"(x), "f"(y)); return r; }
__device__ __forceinline__ float2 unpack2(ull a){ float2 f; asm("mov.b64 {%0, %1}, %2;" : "=f"(f.x), "=f"(f.y) : "l"(a)); return f; }
__device__ __forceinline__ ull fma2(ull a, ull b, ull c){ ull d; asm("fma.rn.f32x2 %0, %1, %2, %3;" : "=l"(d) : "l"(a), "l"(b), "l"(c)); return d; }

// fast activations
__device__ __forceinline__ float sigf(float x){ return __fdividef(1.0f, 1.0f + __expf(-x)); }
__device__ __forceinline__ float tanhfast(float x){ return __fdividef(2.0f, 1.0f + __expf(-2.0f * x)) - 1.0f; }

// one kk's worth of FMAs: 4 gates x 4 row-pairs
__device__ __forceinline__ void step16(ull acc[4][4], const float4& w, const float* sp)
{
  ull s0 = splat2(w.x), s1 = splat2(w.y), s2 = splat2(w.z), s3 = splat2(w.w);
  ulonglong2 ua = *reinterpret_cast<const ulonglong2*>(sp);
  ulonglong2 ub = *reinterpret_cast<const ulonglong2*>(sp + 4);
  acc[0][0] = fma2(ua.x, s0, acc[0][0]);
  acc[1][0] = fma2(ua.x, s1, acc[1][0]);
  acc[2][0] = fma2(ua.x, s2, acc[2][0]);
  acc[3][0] = fma2(ua.x, s3, acc[3][0]);
  acc[0][1] = fma2(ua.y, s0, acc[0][1]);
  acc[1][1] = fma2(ua.y, s1, acc[1][1]);
  acc[2][1] = fma2(ua.y, s2, acc[2][1]);
  acc[3][1] = fma2(ua.y, s3, acc[3][1]);
  acc[0][2] = fma2(ub.x, s0, acc[0][2]);
  acc[1][2] = fma2(ub.x, s1, acc[1][2]);
  acc[2][2] = fma2(ub.x, s2, acc[2][2]);
  acc[3][2] = fma2(ub.x, s3, acc[3][2]);
  acc[0][3] = fma2(ub.y, s0, acc[0][3]);
  acc[1][3] = fma2(ub.y, s1, acc[1][3]);
  acc[2][3] = fma2(ub.y, s2, acc[2][3]);
  acc[3][3] = fma2(ub.y, s3, acc[3][3]);
}

// Accumulate gates over K with an explicit 3-deep rotating weight prefetch:
// the LDG for kk+3 is issued ~3*128 cyc before its use, covering L2-hit latency.
template<int K>
__device__ __forceinline__ void accum(ull acc[4][4], const float4* __restrict__ W4,
                                      const float* src, int k, int rbase)
{
  const float4* wp = W4 + k;
  const float*  sp = src + rbase;
  float4 w0 = __ldg(wp); wp += H;
  float4 w1 = __ldg(wp); wp += H;
  float4 w2 = __ldg(wp); wp += H;
  #pragma unroll 4
  for (int kk = 0; kk < K - 3; ++kk) {
    float4 wn = __ldg(wp); wp += H;
    step16(acc, w0, sp); sp += PITCH;
    w0 = w1; w1 = w2; w2 = wn;
  }
  step16(acc, w0, sp); sp += PITCH;
  step16(acc, w1, sp); sp += PITCH;
  step16(acc, w2, sp);
}

// i,f,g,o -> (c,h) update for 4 row-pairs
__device__ __forceinline__ void cell_update(ull acc[4][4], ull cst[4], ull hn[4])
{
  #pragma unroll
  for (int p = 0; p < 4; ++p) {
    float2 gi = unpack2(acc[0][p]);
    float2 gf = unpack2(acc[1][p]);
    float2 gg = unpack2(acc[2][p]);
    float2 go = unpack2(acc[3][p]);
    float2 c  = unpack2(cst[p]);
    float cx = sigf(gf.x) * c.x + sigf(gi.x) * tanhfast(gg.x);
    float cy = sigf(gf.y) * c.y + sigf(gi.y) * tanhfast(gg.y);
    float hx = sigf(go.x) * tanhfast(cx);
    float hy = sigf(go.y) * tanhfast(cy);
    cst[p] = pack2(cx, cy);
    hn[p]  = pack2(hx, hy);
  }
}

// ---- weight rearrange / bias fuse (tiny, once per launch) ----
__global__ void prep_kernel(const float* __restrict__ Wih0, const float* __restrict__ Whh0,
                            const float* __restrict__ bih0, const float* __restrict__ bhh0,
                            const float* __restrict__ Wih1, const float* __restrict__ Whh1,
                            const float* __restrict__ bih1, const float* __restrict__ bhh1,
                            const float* __restrict__ Wd)
{
  int j = blockIdx.x * blockDim.x + threadIdx.x;
  if (j < GATES * INW) {
    int r = j / INW, kk = j % INW;
    reinterpret_cast<float*>(g_W0i)[(kk * H + (r & 127)) * 4 + (r >> 7)] = Wih0[j];
    return;
  }
  j -= GATES * INW;
  if (j < GATES * H) {
    int r = j / H, kk = j % H;
    reinterpret_cast<float*>(g_W0h)[(kk * H + (r & 127)) * 4 + (r >> 7)] = Whh0[j];
    return;
  }
  j -= GATES * H;
  if (j < GATES * H) {
    int r = j / H, kk = j % H;
    reinterpret_cast<float*>(g_W1i)[(kk * H + (r & 127)) * 4 + (r >> 7)] = Wih1[j];
    return;
  }
  j -= GATES * H;
  if (j < GATES * H) {
    int r = j / H, kk = j % H;
    reinterpret_cast<float*>(g_W1h)[(kk * H + (r & 127)) * 4 + (r >> 7)] = Whh1[j];
    return;
  }
  j -= GATES * H;
  if (j < OUTW * H) { g_WdT[(j % H) * OUTW + (j / H)] = Wd[j]; return; }
  j -= OUTW * H;
  if (j < GATES) { g_b0[j] = bih0[j] + bhh0[j]; return; }
  j -= GATES;
  if (j < GATES) { g_b1[j] = bih1[j] + bhh1[j]; return; }
}

// ---- main persistent-tile LSTM kernel ----
// Block: 16 batch rows for all 65 steps; 256 threads; 2 blocks/SM (16 warps total,
// two INDEPENDENT blocks so barriers never drain the whole SM).
// Thread (k = tid&127 gate unit, rg = tid>>7 -> 8 rows = 4 packed row-pairs).
// h1/h2 double-buffered (2 barriers/step); weights prefetched 3 deep in registers.
__global__ void __launch_bounds__(NTHR, 2)
lstm_main(const float* __restrict__ x, const float* __restrict__ bd, float* __restrict__ out)
{
  __shared__ __align__(16) float uT [INW][PITCH];      // transposed step input
  __shared__ __align__(16) float h1T[2][H][PITCH];     // ping-pong
  __shared__ __align__(16) float h2T[2][H][PITCH];

  const int tid   = threadIdx.x;
  const int k     = tid & 127;
  const int rg    = tid >> 7;
  const int rbase = rg * 8;
  const int row0  = blockIdx.x * BT;

  for (int i = tid; i < 2 * H * PITCH; i += NTHR) { (&h1T[0][0][0])[i] = 0.0f; (&h2T[0][0][0])[i] = 0.0f; }

  ull c1[4], c2[4];
  #pragma unroll
  for (int p = 0; p < 4; ++p) { c1[p] = 0ull; c2[p] = 0ull; }

  ull b0p[4], b1p[4];
  #pragma unroll
  for (int g = 0; g < 4; ++g) { b0p[g] = splat2(g_b0[g * H + k]); b1p[g] = splat2(g_b1[g * H + k]); }
  const float bdv = (k < OUTW) ? bd[k] : 0.0f;

  // prestage u for step 0
  for (int i = tid; i < BT * INW; i += NTHR) {
    int r = i / INW, c = i % INW;
    uT[c][r] = x[(size_t)(row0 + r) * (TSEQ * INW) + c];
  }
  __syncthreads();

  for (int s = 0; s < NSTEP; ++s) {
    const int rd = s & 1, wr = rd ^ 1;
    ull acc[4][4], hn[4];

    // ---- layer 0 : gates = u@Wih0^T + h1@Whh0^T + b0 ----
    #pragma unroll
    for (int g = 0; g < 4; ++g)
      #pragma unroll
      for (int p = 0; p < 4; ++p) acc[g][p] = b0p[g];
    accum<INW>(acc, g_W0i, &uT[0][0],      k, rbase);
    accum<H>  (acc, g_W0h, &h1T[rd][0][0], k, rbase);
    cell_update(acc, c1, hn);
    *reinterpret_cast<ulonglong2*>(&h1T[wr][k][rbase])     = make_ulonglong2(hn[0], hn[1]);
    *reinterpret_cast<ulonglong2*>(&h1T[wr][k][rbase + 4]) = make_ulonglong2(hn[2], hn[3]);
    __syncthreads();   // barrier A: h1[wr] visible; all reads of uT done

    // stage u for next step (x path); rollout pose handled after dense head
    if (s + 1 <= TSEQ) {
      int t = (s + 1 < TSEQ) ? (s + 1) : (TSEQ - 1);
      for (int i = tid; i < BT * INW; i += NTHR) {
        int r = i / INW, c = i % INW;
        uT[c][r] = x[(size_t)(row0 + r) * (TSEQ * INW) + t * INW + c];
      }
    }

    // ---- layer 1 : gates = h1@Wih1^T + h2@Whh1^T + b1 ----
    #pragma unroll
    for (int g = 0; g < 4; ++g)
      #pragma unroll
      for (int p = 0; p < 4; ++p) acc[g][p] = b1p[g];
    accum<H>(acc, g_W1i, &h1T[wr][0][0], k, rbase);
    accum<H>(acc, g_W1h, &h2T[rd][0][0], k, rbase);
    cell_update(acc, c2, hn);
    *reinterpret_cast<ulonglong2*>(&h2T[wr][k][rbase])     = make_ulonglong2(hn[0], hn[1]);
    *reinterpret_cast<ulonglong2*>(&h2T[wr][k][rbase + 4]) = make_ulonglong2(hn[2], hn[3]);
    __syncthreads();   // barrier B: h2[wr] visible; u staging visible

    // ---- dense head (steps 50..64): pose = h2 @ Wd^T + bd ----
    if (s >= TSEQ) {
      const int so = s - TSEQ;
      if (k < OUTW) {
        ull pa[4];
        #pragma unroll
        for (int p = 0; p < 4; ++p) pa[p] = splat2(bdv);
        const float* wd = &g_WdT[k];
        const float* sp = &h2T[wr][0][rbase];
        #pragma unroll 4
        for (int kk = 0; kk < H; ++kk) {
          ull w2 = splat2(__ldg(wd));  wd += OUTW;
          ulonglong2 ua = *reinterpret_cast<const ulonglong2*>(sp);
          ulonglong2 ub = *reinterpret_cast<const ulonglong2*>(sp + 4);
          sp += PITCH;
          pa[0] = fma2(ua.x, w2, pa[0]);
          pa[1] = fma2(ua.y, w2, pa[1]);
          pa[2] = fma2(ub.x, w2, pa[2]);
          pa[3] = fma2(ub.y, w2, pa[3]);
        }
        #pragma unroll
        for (int p = 0; p < 4; ++p) {
          float2 f = unpack2(pa[p]);
          int rloc = rbase + 2 * p;
          size_t r = (size_t)(row0 + rloc);
          out[ r      * (RSTEPS * OUTW) + so * OUTW + k] = f.x;
          out[(r + 1) * (RSTEPS * OUTW) + so * OUTW + k] = f.y;
          uT[k][rloc]     = f.x;   // pose becomes next step's u[0..65]; u[66..85] keeps cond
          uT[k][rloc + 1] = f.y;
        }
      }
      __syncthreads();  // barrier C: pose in uT visible for next layer0
    }
  }
}

extern "C" void kernel_launch(void* const* d_in, const int* in_sizes, int n_in,
                              void* d_out, int out_size)
{
  const float* x    = (const float*)d_in[0];
  const float* Wih0 = (const float*)d_in[1];
  const float* Whh0 = (const float*)d_in[2];
  const float* bih0 = (const float*)d_in[3];
  const float* bhh0 = (const float*)d_in[4];
  const float* Wih1 = (const float*)d_in[5];
  const float* Whh1 = (const float*)d_in[6];
  const float* bih1 = (const float*)d_in[7];
  const float* bhh1 = (const float*)d_in[8];
  const float* Wd   = (const float*)d_in[9];
  const float* bd   = (const float*)d_in[10];
  float* out = (float*)d_out;

  const int B = in_sizes[0] / (TSEQ * INW);   // 8192

  const int prep_n = GATES * INW + 3 * GATES * H + OUTW * H + 2 * GATES;
  prep_kernel<<<(prep_n + 255) / 256, 256>>>(Wih0, Whh0, bih0, bhh0,
                                             Wih1, Whh1, bih1, bhh1, Wd);
  lstm_main<<<B / BT, NTHR>>>(x, bd, out);
}

// round 5
// speedup vs baseline: 1.2173x; 1.0007x over previous
#include <cuda_runtime.h>
#include <cstdint>

#define H      128
#define INW    86
#define OUTW   66
#define GATES  512
#define TSEQ   50
#define NSTEP  65   // 50 scan + 1 replay of x[:,49] + 14 rollout
#define RSTEPS 15
#define BT     16   // batch rows per block
#define PITCH  20   // padded row pitch: multiple of 4 for 16B-aligned pair loads
#define NTHR   256

typedef unsigned long long ull;

// ---- weight scratch: gate-interleaved float4 [kk][k] = {w_i, w_f, w_g, w_o} ----
__device__ float4 g_W0i[INW * H];   // from Wih0 [512][86]
__device__ float4 g_W0h[H   * H];   // from Whh0 [512][128]
__device__ float4 g_W1i[H   * H];   // from Wih1 [512][128]
__device__ float4 g_W1h[H   * H];   // from Whh1 [512][128]
__device__ float  g_WdT[H * OUTW];  // Wd^T : [kk][o]
__device__ float  g_b0[GATES];
__device__ float  g_b1[GATES];

// ---- packed f32x2 helpers (Blackwell FFMA2 via PTX) ----
__device__ __forceinline__ ull splat2(float v){ ull r; asm("mov.b64 %0, {%1, %1};" : "=l"(r) : "f"(v)); return r; }
__device__ __forceinline__ ull pack2(float x, float y){ ull r; asm("mov.b64 %0, {%1, %2};" : "=l"(r) : "f"(x), "f"(y)); return r; }
__device__ __forceinline__ float2 unpack2(ull a){ float2 f; asm("mov.b64 {%0, %1}, %2;" : "=f"(f.x), "=f"(f.y) : "l"(a)); return f; }
__device__ __forceinline__ ull fma2(ull a, ull b, ull c){ ull d; asm("fma.rn.f32x2 %0, %1, %2, %3;" : "=l"(d) : "l"(a), "l"(b), "l"(c)); return d; }

// fast activations
__device__ __forceinline__ float sigf(float x){ return __fdividef(1.0f, 1.0f + __expf(-x)); }
__device__ __forceinline__ float tanhfast(float x){ return __fdividef(2.0f, 1.0f + __expf(-2.0f * x)) - 1.0f; }

// one kk's worth of FMAs: 4 gates x 4 row-pairs
__device__ __forceinline__ void step16(ull acc[4][4], const float4& w, const float* sp)
{
  ull s0 = splat2(w.x), s1 = splat2(w.y), s2 = splat2(w.z), s3 = splat2(w.w);
  ulonglong2 ua = *reinterpret_cast<const ulonglong2*>(sp);
  ulonglong2 ub = *reinterpret_cast<const ulonglong2*>(sp + 4);
  acc[0][0] = fma2(ua.x, s0, acc[0][0]);
  acc[1][0] = fma2(ua.x, s1, acc[1][0]);
  acc[2][0] = fma2(ua.x, s2, acc[2][0]);
  acc[3][0] = fma2(ua.x, s3, acc[3][0]);
  acc[0][1] = fma2(ua.y, s0, acc[0][1]);
  acc[1][1] = fma2(ua.y, s1, acc[1][1]);
  acc[2][1] = fma2(ua.y, s2, acc[2][1]);
  acc[3][1] = fma2(ua.y, s3, acc[3][1]);
  acc[0][2] = fma2(ub.x, s0, acc[0][2]);
  acc[1][2] = fma2(ub.x, s1, acc[1][2]);
  acc[2][2] = fma2(ub.x, s2, acc[2][2]);
  acc[3][2] = fma2(ub.x, s3, acc[3][2]);
  acc[0][3] = fma2(ub.y, s0, acc[0][3]);
  acc[1][3] = fma2(ub.y, s1, acc[1][3]);
  acc[2][3] = fma2(ub.y, s2, acc[2][3]);
  acc[3][3] = fma2(ub.y, s3, acc[3][3]);
}

// Accumulate gates over K with an explicit 3-deep rotating weight prefetch:
// the LDG for kk+3 is issued ~3*128 cyc before its use, covering L2-hit latency.
template<int K>
__device__ __forceinline__ void accum(ull acc[4][4], const float4* __restrict__ W4,
                                      const float* src, int k, int rbase)
{
  const float4* wp = W4 + k;
  const float*  sp = src + rbase;
  float4 w0 = __ldg(wp); wp += H;
  float4 w1 = __ldg(wp); wp += H;
  float4 w2 = __ldg(wp); wp += H;
  #pragma unroll 4
  for (int kk = 0; kk < K - 3; ++kk) {
    float4 wn = __ldg(wp); wp += H;
    step16(acc, w0, sp); sp += PITCH;
    w0 = w1; w1 = w2; w2 = wn;
  }
  step16(acc, w0, sp); sp += PITCH;
  step16(acc, w1, sp); sp += PITCH;
  step16(acc, w2, sp);
}

// i,f,g,o -> (c,h) update for 4 row-pairs
__device__ __forceinline__ void cell_update(ull acc[4][4], ull cst[4], ull hn[4])
{
  #pragma unroll
  for (int p = 0; p < 4; ++p) {
    float2 gi = unpack2(acc[0][p]);
    float2 gf = unpack2(acc[1][p]);
    float2 gg = unpack2(acc[2][p]);
    float2 go = unpack2(acc[3][p]);
    float2 c  = unpack2(cst[p]);
    float cx = sigf(gf.x) * c.x + sigf(gi.x) * tanhfast(gg.x);
    float cy = sigf(gf.y) * c.y + sigf(gi.y) * tanhfast(gg.y);
    float hx = sigf(go.x) * tanhfast(cx);
    float hy = sigf(go.y) * tanhfast(cy);
    cst[p] = pack2(cx, cy);
    hn[p]  = pack2(hx, hy);
  }
}

// ---- weight rearrange / bias fuse (tiny, once per launch) ----
__global__ void prep_kernel(const float* __restrict__ Wih0, const float* __restrict__ Whh0,
                            const float* __restrict__ bih0, const float* __restrict__ bhh0,
                            const float* __restrict__ Wih1, const float* __restrict__ Whh1,
                            const float* __restrict__ bih1, const float* __restrict__ bhh1,
                            const float* __restrict__ Wd)
{
  int j = blockIdx.x * blockDim.x + threadIdx.x;
  if (j < GATES * INW) {
    int r = j / INW, kk = j % INW;
    reinterpret_cast<float*>(g_W0i)[(kk * H + (r & 127)) * 4 + (r >> 7)] = Wih0[j];
    return;
  }
  j -= GATES * INW;
  if (j < GATES * H) {
    int r = j / H, kk = j % H;
    reinterpret_cast<float*>(g_W0h)[(kk * H + (r & 127)) * 4 + (r >> 7)] = Whh0[j];
    return;
  }
  j -= GATES * H;
  if (j < GATES * H) {
    int r = j / H, kk = j % H;
    reinterpret_cast<float*>(g_W1i)[(kk * H + (r & 127)) * 4 + (r >> 7)] = Wih1[j];
    return;
  }
  j -= GATES * H;
  if (j < GATES * H) {
    int r = j / H, kk = j % H;
    reinterpret_cast<float*>(g_W1h)[(kk * H + (r & 127)) * 4 + (r >> 7)] = Whh1[j];
    return;
  }
  j -= GATES * H;
  if (j < OUTW * H) { g_WdT[(j % H) * OUTW + (j / H)] = Wd[j]; return; }
  j -= OUTW * H;
  if (j < GATES) { g_b0[j] = bih0[j] + bhh0[j]; return; }
  j -= GATES;
  if (j < GATES) { g_b1[j] = bih1[j] + bhh1[j]; return; }
}

// ---- main persistent-tile LSTM kernel ----
// Block: 16 batch rows for all 65 steps; 256 threads; 2 blocks/SM (16 warps total,
// two INDEPENDENT blocks so barriers never drain the whole SM).
// Thread (k = tid&127 gate unit, rg = tid>>7 -> 8 rows = 4 packed row-pairs).
// h1/h2 double-buffered (2 barriers/step); weights prefetched 3 deep in registers.
__global__ void __launch_bounds__(NTHR, 2)
lstm_main(const float* __restrict__ x, const float* __restrict__ bd, float* __restrict__ out)
{
  __shared__ __align__(16) float uT [INW][PITCH];      // transposed step input
  __shared__ __align__(16) float h1T[2][H][PITCH];     // ping-pong
  __shared__ __align__(16) float h2T[2][H][PITCH];

  const int tid   = threadIdx.x;
  const int k     = tid & 127;
  const int rg    = tid >> 7;
  const int rbase = rg * 8;
  const int row0  = blockIdx.x * BT;

  for (int i = tid; i < 2 * H * PITCH; i += NTHR) { (&h1T[0][0][0])[i] = 0.0f; (&h2T[0][0][0])[i] = 0.0f; }

  ull c1[4], c2[4];
  #pragma unroll
  for (int p = 0; p < 4; ++p) { c1[p] = 0ull; c2[p] = 0ull; }

  ull b0p[4], b1p[4];
  #pragma unroll
  for (int g = 0; g < 4; ++g) { b0p[g] = splat2(g_b0[g * H + k]); b1p[g] = splat2(g_b1[g * H + k]); }
  const float bdv = (k < OUTW) ? bd[k] : 0.0f;

  // prestage u for step 0
  for (int i = tid; i < BT * INW; i += NTHR) {
    int r = i / INW, c = i % INW;
    uT[c][r] = x[(size_t)(row0 + r) * (TSEQ * INW) + c];
  }
  __syncthreads();

  for (int s = 0; s < NSTEP; ++s) {
    const int rd = s & 1, wr = rd ^ 1;
    ull acc[4][4], hn[4];

    // ---- layer 0 : gates = u@Wih0^T + h1@Whh0^T + b0 ----
    #pragma unroll
    for (int g = 0; g < 4; ++g)
      #pragma unroll
      for (int p = 0; p < 4; ++p) acc[g][p] = b0p[g];
    accum<INW>(acc, g_W0i, &uT[0][0],      k, rbase);
    accum<H>  (acc, g_W0h, &h1T[rd][0][0], k, rbase);
    cell_update(acc, c1, hn);
    *reinterpret_cast<ulonglong2*>(&h1T[wr][k][rbase])     = make_ulonglong2(hn[0], hn[1]);
    *reinterpret_cast<ulonglong2*>(&h1T[wr][k][rbase + 4]) = make_ulonglong2(hn[2], hn[3]);
    __syncthreads();   // barrier A: h1[wr] visible; all reads of uT done

    // stage u for next step (x path); rollout pose handled after dense head
    if (s + 1 <= TSEQ) {
      int t = (s + 1 < TSEQ) ? (s + 1) : (TSEQ - 1);
      for (int i = tid; i < BT * INW; i += NTHR) {
        int r = i / INW, c = i % INW;
        uT[c][r] = x[(size_t)(row0 + r) * (TSEQ * INW) + t * INW + c];
      }
    }

    // ---- layer 1 : gates = h1@Wih1^T + h2@Whh1^T + b1 ----
    #pragma unroll
    for (int g = 0; g < 4; ++g)
      #pragma unroll
      for (int p = 0; p < 4; ++p) acc[g][p] = b1p[g];
    accum<H>(acc, g_W1i, &h1T[wr][0][0], k, rbase);
    accum<H>(acc, g_W1h, &h2T[rd][0][0], k, rbase);
    cell_update(acc, c2, hn);
    *reinterpret_cast<ulonglong2*>(&h2T[wr][k][rbase])     = make_ulonglong2(hn[0], hn[1]);
    *reinterpret_cast<ulonglong2*>(&h2T[wr][k][rbase + 4]) = make_ulonglong2(hn[2], hn[3]);
    __syncthreads();   // barrier B: h2[wr] visible; u staging visible

    // ---- dense head (steps 50..64): pose = h2 @ Wd^T + bd ----
    if (s >= TSEQ) {
      const int so = s - TSEQ;
      if (k < OUTW) {
        ull pa[4];
        #pragma unroll
        for (int p = 0; p < 4; ++p) pa[p] = splat2(bdv);
        const float* wd = &g_WdT[k];
        const float* sp = &h2T[wr][0][rbase];
        #pragma unroll 4
        for (int kk = 0; kk < H; ++kk) {
          ull w2 = splat2(__ldg(wd));  wd += OUTW;
          ulonglong2 ua = *reinterpret_cast<const ulonglong2*>(sp);
          ulonglong2 ub = *reinterpret_cast<const ulonglong2*>(sp + 4);
          sp += PITCH;
          pa[0] = fma2(ua.x, w2, pa[0]);
          pa[1] = fma2(ua.y, w2, pa[1]);
          pa[2] = fma2(ub.x, w2, pa[2]);
          pa[3] = fma2(ub.y, w2, pa[3]);
        }
        #pragma unroll
        for (int p = 0; p < 4; ++p) {
          float2 f = unpack2(pa[p]);
          int rloc = rbase + 2 * p;
          size_t r = (size_t)(row0 + rloc);
          out[ r      * (RSTEPS * OUTW) + so * OUTW + k] = f.x;
          out[(r + 1) * (RSTEPS * OUTW) + so * OUTW + k] = f.y;
          uT[k][rloc]     = f.x;   // pose becomes next step's u[0..65]; u[66..85] keeps cond
          uT[k][rloc + 1] = f.y;
        }
      }
      __syncthreads();  // barrier C: pose in uT visible for next layer0
    }
  }
}

extern "C" void kernel_launch(void* const* d_in, const int* in_sizes, int n_in,
                              void* d_out, int out_size)
{
  const float* x    = (const float*)d_in[0];
  const float* Wih0 = (const float*)d_in[1];
  const float* Whh0 = (const float*)d_in[2];
  const float* bih0 = (const float*)d_in[3];
  const float* bhh0 = (const float*)d_in[4];
  const float* Wih1 = (const float*)d_in[5];
  const float* Whh1 = (const float*)d_in[6];
  const float* bih1 = (const float*)d_in[7];
  const float* bhh1 = (const float*)d_in[8];
  const float* Wd   = (const float*)d_in[9];
  const float* bd   = (const float*)d_in[10];
  float* out = (float*)d_out;

  const int B = in_sizes[0] / (TSEQ * INW);   // 8192

  const int prep_n = GATES * INW + 3 * GATES * H + OUTW * H + 2 * GATES;
  prep_kernel<<<(prep_n + 255) / 256, 256>>>(Wih0, Whh0, bih0, bhh0,
                                             Wih1, Whh1, bih1, bhh1, Wd);
  lstm_main<<<B / BT, NTHR>>>(x, bd, out);
}